// round 3
// baseline (speedup 1.0000x reference)
#include <cuda_runtime.h>
#include <cstdint>

// Problem constants
#define BATCH 2
#define NSEQ  2048
#define DMODEL 1024
#define NHEAD 16
#define DK    64
#define MROWS (BATCH * NSEQ)   // 4096

// Scratch (allocation-free rule: __device__ globals)
__device__ float g_Q[MROWS * DMODEL];
__device__ float g_K[MROWS * DMODEL];
__device__ float g_V[MROWS * DMODEL];
__device__ float g_C[MROWS * DMODEL];

// ---------------------------------------------------------------------------
// GEMM:  C[m][n] = sum_k A[m][k] * W[n][k]  (+ bias[n])
// A: [MROWS, DMODEL], W: [DMODEL, DMODEL] row-major. 64x64 tile, BK=16,
// 256 threads, 4x4 micro-tile per thread.
// ---------------------------------------------------------------------------
template <bool HAS_BIAS>
__global__ __launch_bounds__(256)
void gemm_nt_kernel(const float* __restrict__ A, const float* __restrict__ W,
                    float* __restrict__ C, const float* __restrict__ bias) {
    __shared__ float As[16][64];
    __shared__ float Bs[16][64];

    const int tid = threadIdx.x;
    const int tx = tid & 15;         // 0..15 -> n
    const int ty = tid >> 4;         // 0..15 -> m
    const int m0 = blockIdx.y * 64;
    const int n0 = blockIdx.x * 64;

    const int lrow = tid >> 2;       // 0..63
    const int lk4  = (tid & 3) * 4;  // 0,4,8,12

    float c[4][4];
#pragma unroll
    for (int i = 0; i < 4; i++)
#pragma unroll
        for (int j = 0; j < 4; j++) c[i][j] = 0.0f;

    for (int k0 = 0; k0 < DMODEL; k0 += 16) {
        // Load A tile (64 x 16) and W tile (64 x 16), transposed into smem
        float4 av = *(const float4*)&A[(size_t)(m0 + lrow) * DMODEL + k0 + lk4];
        As[lk4 + 0][lrow] = av.x;
        As[lk4 + 1][lrow] = av.y;
        As[lk4 + 2][lrow] = av.z;
        As[lk4 + 3][lrow] = av.w;
        float4 bv = *(const float4*)&W[(size_t)(n0 + lrow) * DMODEL + k0 + lk4];
        Bs[lk4 + 0][lrow] = bv.x;
        Bs[lk4 + 1][lrow] = bv.y;
        Bs[lk4 + 2][lrow] = bv.z;
        Bs[lk4 + 3][lrow] = bv.w;
        __syncthreads();

#pragma unroll
        for (int kk = 0; kk < 16; kk++) {
            float a[4], b[4];
            *(float4*)a = *(const float4*)&As[kk][ty * 4];
            *(float4*)b = *(const float4*)&Bs[kk][tx * 4];
#pragma unroll
            for (int i = 0; i < 4; i++)
#pragma unroll
                for (int j = 0; j < 4; j++) c[i][j] += a[i] * b[j];
        }
        __syncthreads();
    }

    float4 bb = make_float4(0.f, 0.f, 0.f, 0.f);
    if (HAS_BIAS) bb = *(const float4*)&bias[n0 + tx * 4];

#pragma unroll
    for (int i = 0; i < 4; i++) {
        float4 o;
        o.x = c[i][0] + bb.x;
        o.y = c[i][1] + bb.y;
        o.z = c[i][2] + bb.z;
        o.w = c[i][3] + bb.w;
        *(float4*)&C[(size_t)(m0 + ty * 4 + i) * DMODEL + n0 + tx * 4] = o;
    }
}

// ---------------------------------------------------------------------------
// Flash attention, fp32. One query row per thread. 128 rows/block, 64
// keys per tile. Causal + key-padding mask. Online softmax per row
// (thread-private: no cross-thread reductions).
// Writes ctx in [B, N, D] layout (head h occupies cols h*DK..h*DK+63).
// ---------------------------------------------------------------------------
__global__ __launch_bounds__(128)
void attn_kernel(const float* __restrict__ Q, const float* __restrict__ K,
                 const float* __restrict__ V, const int* __restrict__ amask,
                 float* __restrict__ C) {
    __shared__ float Ks[64 * 64];
    __shared__ float Vs[64 * 64];
    __shared__ float padAdd[64];

    const int tid = threadIdx.x;
    const int bh = blockIdx.y;            // 0..31
    const int b = bh / NHEAD;
    const int h = bh % NHEAD;
    const int m0 = blockIdx.x * 128;
    const int qi = m0 + tid;              // this thread's query row

    const float* __restrict__ qrow = Q + ((size_t)(b * NSEQ + qi)) * DMODEL + h * DK;

    float s[64];
    float O[64];
    float mcur = -1e30f;
    float l = 0.0f;
#pragma unroll
    for (int d = 0; d < 64; d++) O[d] = 0.0f;

    const int ntiles = m0 / 64 + 2;       // key tiles covering keys <= m0+127

    for (int t = 0; t < ntiles; t++) {
        const int kt = t * 64;
        __syncthreads();
        // Load K, V tiles (64 keys x 64 dims), float4-coalesced.
        for (int f = tid; f < 64 * 16; f += 128) {
            const int j = f >> 4;
            const int d4 = f & 15;
            const size_t rbase = ((size_t)(b * NSEQ + kt + j)) * DMODEL + h * DK;
            ((float4*)Ks)[j * 16 + d4] = *(const float4*)&K[rbase + d4 * 4];
            ((float4*)Vs)[j * 16 + d4] = *(const float4*)&V[rbase + d4 * 4];
        }
        if (tid < 64)
            padAdd[tid] = amask[b * NSEQ + kt + tid] ? 0.0f : -1e30f;
        __syncthreads();

#pragma unroll
        for (int j = 0; j < 64; j++) s[j] = 0.0f;

        // S = q . K^T  (K reads are warp-uniform -> broadcast, conflict-free)
#pragma unroll
        for (int c4 = 0; c4 < 4; c4++) {
            float4 q[4];
#pragma unroll
            for (int i = 0; i < 4; i++)
                q[i] = *(const float4*)&qrow[c4 * 16 + i * 4];
#pragma unroll
            for (int j = 0; j < 64; j++) {
                const float4* kr = (const float4*)&Ks[j * 64 + c4 * 16];
#pragma unroll
                for (int i = 0; i < 4; i++) {
                    float4 kv = kr[i];
                    s[j] += q[i].x * kv.x;
                    s[j] += q[i].y * kv.y;
                    s[j] += q[i].z * kv.z;
                    s[j] += q[i].w * kv.w;
                }
            }
        }

        // Mask + scale + row max
        float m_new = mcur;
#pragma unroll
        for (int j = 0; j < 64; j++) {
            float sj = s[j] * 0.125f + padAdd[j];   // scale = 1/sqrt(64)
            if (kt + j > qi) sj = -1e30f;           // causal
            s[j] = sj;
            m_new = fmaxf(m_new, sj);
        }

        const float corr = __expf(mcur - m_new);
        mcur = m_new;
        l *= corr;
#pragma unroll
        for (int d = 0; d < 64; d++) O[d] *= corr;

#pragma unroll
        for (int j = 0; j < 64; j++) {
            float p = __expf(s[j] - m_new);
            l += p;
            s[j] = p;
        }

        // O += P @ V (V reads warp-uniform broadcast)
#pragma unroll
        for (int j = 0; j < 64; j++) {
            const float pj = s[j];
            const float4* vr = (const float4*)&Vs[j * 64];
#pragma unroll
            for (int d4 = 0; d4 < 16; d4++) {
                float4 vv = vr[d4];
                O[d4 * 4 + 0] += pj * vv.x;
                O[d4 * 4 + 1] += pj * vv.y;
                O[d4 * 4 + 2] += pj * vv.z;
                O[d4 * 4 + 3] += pj * vv.w;
            }
        }
    }

    const float inv = 1.0f / l;
    float* __restrict__ co = C + ((size_t)(b * NSEQ + qi)) * DMODEL + h * DK;
#pragma unroll
    for (int d4 = 0; d4 < 16; d4++) {
        float4 o4;
        o4.x = O[d4 * 4 + 0] * inv;
        o4.y = O[d4 * 4 + 1] * inv;
        o4.z = O[d4 * 4 + 2] * inv;
        o4.w = O[d4 * 4 + 3] * inv;
        ((float4*)co)[d4] = o4;
    }
}

// ---------------------------------------------------------------------------
// Launch
// ---------------------------------------------------------------------------
extern "C" void kernel_launch(void* const* d_in, const int* in_sizes, int n_in,
                              void* d_out, int out_size) {
    const float* x     = (const float*)d_in[0];
    const int*   amask = (const int*)d_in[1];
    const float* W_Q   = (const float*)d_in[2];
    const float* W_K   = (const float*)d_in[3];
    const float* W_V   = (const float*)d_in[4];
    const float* W_out = (const float*)d_in[5];
    const float* b_out = (const float*)d_in[6];
    float* out = (float*)d_out;

    float *gQ, *gK, *gV, *gC;
    cudaGetSymbolAddress((void**)&gQ, g_Q);
    cudaGetSymbolAddress((void**)&gK, g_K);
    cudaGetSymbolAddress((void**)&gV, g_V);
    cudaGetSymbolAddress((void**)&gC, g_C);

    dim3 ggrid(DMODEL / 64, MROWS / 64);   // (16, 64)
    gemm_nt_kernel<false><<<ggrid, 256>>>(x, W_Q, gQ, nullptr);
    gemm_nt_kernel<false><<<ggrid, 256>>>(x, W_K, gK, nullptr);
    gemm_nt_kernel<false><<<ggrid, 256>>>(x, W_V, gV, nullptr);

    dim3 agrid(NSEQ / 128, BATCH * NHEAD); // (16, 32)
    attn_kernel<<<agrid, 128>>>(gQ, gK, gV, amask, gC);

    gemm_nt_kernel<true><<<ggrid, 256>>>(gC, W_out, out, b_out);
}

// round 5
// speedup vs baseline: 4.7883x; 4.7883x over previous
#include <cuda_runtime.h>
#include <cuda_bf16.h>
#include <cstdint>

// Problem constants
#define BATCH 2
#define NSEQ  2048
#define DMODEL 1024
#define NHEAD 16
#define DK    64
#define MROWS (BATCH * NSEQ)   // 4096

typedef __nv_bfloat16 bf16;

// ---------------------------------------------------------------------------
// Scratch (allocation-free rule: __device__ globals)
// Split arrays: [rows][2048] = [hi(1024) | lo(1024)]
// Q/K/V arrays: per-head concat: [rows][2048], head h at cols h*128: hi dk
// 0..63 then lo dk 0..63.
// ---------------------------------------------------------------------------
__device__ bf16 g_xs [MROWS * 2048];
__device__ bf16 g_wqs[DMODEL * 2048];
__device__ bf16 g_wks[DMODEL * 2048];
__device__ bf16 g_wvs[DMODEL * 2048];
__device__ bf16 g_wos[DMODEL * 2048];
__device__ bf16 g_qs [MROWS * 2048];
__device__ bf16 g_ks [MROWS * 2048];
__device__ bf16 g_vs [MROWS * 2048];
__device__ bf16 g_cs [MROWS * 2048];

// ---------------------------------------------------------------------------
// PTX helpers (all base compute_103 features: no 'a'-gated instructions)
// ---------------------------------------------------------------------------
__device__ __forceinline__ uint32_t smem_u32(const void* p) {
    uint32_t a;
    asm("{ .reg .u64 t; cvta.to.shared.u64 t, %1; cvt.u32.u64 %0, t; }"
        : "=r"(a) : "l"(p));
    return a;
}
#define CP16(dst, src) \
    asm volatile("cp.async.cg.shared.global [%0], [%1], 16;" \
                 :: "r"(dst), "l"(src))
#define CP_COMMIT() asm volatile("cp.async.commit_group;" ::: "memory")
#define CP_WAIT0()  asm volatile("cp.async.wait_group 0;" ::: "memory")
#define CP_WAIT1()  asm volatile("cp.async.wait_group 1;" ::: "memory")

__device__ __forceinline__ void ldsm4(uint32_t addr, uint32_t& r0, uint32_t& r1,
                                      uint32_t& r2, uint32_t& r3) {
    asm volatile("ldmatrix.sync.aligned.m8n8.x4.shared.b16 {%0,%1,%2,%3}, [%4];"
                 : "=r"(r0), "=r"(r1), "=r"(r2), "=r"(r3) : "r"(addr));
}
__device__ __forceinline__ void ldsm4t(uint32_t addr, uint32_t& r0, uint32_t& r1,
                                       uint32_t& r2, uint32_t& r3) {
    asm volatile("ldmatrix.sync.aligned.m8n8.x4.trans.shared.b16 {%0,%1,%2,%3}, [%4];"
                 : "=r"(r0), "=r"(r1), "=r"(r2), "=r"(r3) : "r"(addr));
}
// D += A*B  (m16n8k16, bf16 in, fp32 accum)
__device__ __forceinline__ void mma16816(float* c, uint32_t a0, uint32_t a1,
                                         uint32_t a2, uint32_t a3,
                                         uint32_t b0, uint32_t b1) {
    asm volatile(
        "mma.sync.aligned.m16n8k16.row.col.f32.bf16.bf16.f32 "
        "{%0,%1,%2,%3}, {%4,%5,%6,%7}, {%8,%9}, {%0,%1,%2,%3};"
        : "+f"(c[0]), "+f"(c[1]), "+f"(c[2]), "+f"(c[3])
        : "r"(a0), "r"(a1), "r"(a2), "r"(a3), "r"(b0), "r"(b1));
}
__device__ __forceinline__ uint32_t packbf(float a, float b) {
    __nv_bfloat162 t = __floats2bfloat162_rn(a, b);  // .x = a (low), .y = b
    return *(uint32_t*)&t;
}

// ---------------------------------------------------------------------------
// fp32 [R][1024] -> bf16 [R][2048] = [hi | lo]
// ---------------------------------------------------------------------------
__global__ __launch_bounds__(256)
void split_kernel(const float* __restrict__ in, bf16* __restrict__ out, int n4) {
    int i = blockIdx.x * blockDim.x + threadIdx.x;
    if (i >= n4) return;
    float4 v = ((const float4*)in)[i];
    int r = i >> 8;                 // /(1024/4)
    int c = (i & 255) * 4;
    bf16 h0 = __float2bfloat16_rn(v.x), h1 = __float2bfloat16_rn(v.y);
    bf16 h2 = __float2bfloat16_rn(v.z), h3 = __float2bfloat16_rn(v.w);
    uint32_t* oh = (uint32_t*)(out + (size_t)r * 2048 + c);
    uint32_t* ol = (uint32_t*)(out + (size_t)r * 2048 + 1024 + c);
    oh[0] = packbf(__bfloat162float(h0), __bfloat162float(h1));
    oh[1] = packbf(__bfloat162float(h2), __bfloat162float(h3));
    ol[0] = packbf(v.x - __bfloat162float(h0), v.y - __bfloat162float(h1));
    ol[1] = packbf(v.z - __bfloat162float(h2), v.w - __bfloat162float(h3));
}

// ---------------------------------------------------------------------------
// Tensor-core GEMM: C[m][n] = sum over fp32-split 3-term concat (K'=3072)
//   chunks c: 0-15 -> Ah*Bh, 16-31 -> Al*Bh, 32-47 -> Ah*Bl
// A: [4096][2048] split, B: [1024][2048] split.
// CTA 128x128, 256 thr, 8 warps (2x4), warp tile 64x32. cp.async dbl-buffer.
// EPI 0: bf16 per-head concat out (Q/K/V). EPI 1: fp32 + bias.
// ---------------------------------------------------------------------------
#define G_STRIDE 144          // bytes per smem row (64 halves + pad)
#define G_STAGE  (128 * G_STRIDE)      // 18432 per matrix
#define G_SMEM   (4 * G_STAGE)         // A0,B0,A1,B1 = 73728
#define NCHUNK 48

__device__ __forceinline__ void gemm_prefetch(const bf16* A, const bf16* B,
                                              int m0, int n0, int c,
                                              uint32_t sa, uint32_t sb, int tid) {
    int ac = (c < 32) ? c * 64 : (c - 32) * 64;
    int bc = (c < 16) ? c * 64 : (c < 32 ? (c - 16) * 64 : (c - 32) * 64 + 1024);
#pragma unroll
    for (int it = 0; it < 4; it++) {
        int idx = tid + it * 256;
        int row = idx >> 3, seg = idx & 7;
        CP16(sa + row * G_STRIDE + seg * 16,
             A + (size_t)(m0 + row) * 2048 + ac + seg * 8);
    }
#pragma unroll
    for (int it = 0; it < 4; it++) {
        int idx = tid + it * 256;
        int row = idx >> 3, seg = idx & 7;
        CP16(sb + row * G_STRIDE + seg * 16,
             B + (size_t)(n0 + row) * 2048 + bc + seg * 8);
    }
}

template <int EPI>
__global__ __launch_bounds__(256)
void mma_gemm(const bf16* __restrict__ A, const bf16* __restrict__ B,
              float* __restrict__ Cf, bf16* __restrict__ Cb,
              const float* __restrict__ bias) {
    extern __shared__ char smem[];
    const uint32_t sbase = smem_u32(smem);
    const int tid = threadIdx.x;
    const int w = tid >> 5, L = tid & 31;
    const int g = L >> 2, cq = L & 3;
    const int wm = w >> 2, wn = w & 3;
    const int m0 = blockIdx.y * 128, n0 = blockIdx.x * 128;
    const int quad = L >> 3, l8 = L & 7;

    float acc[4][4][4];
#pragma unroll
    for (int i = 0; i < 4; i++)
#pragma unroll
        for (int j = 0; j < 4; j++)
#pragma unroll
            for (int k = 0; k < 4; k++) acc[i][j][k] = 0.0f;

    gemm_prefetch(A, B, m0, n0, 0, sbase, sbase + G_STAGE, tid);
    CP_COMMIT();

    for (int c = 0; c < NCHUNK; c++) {
        const int st = c & 1;
        const uint32_t sa = sbase + st * 2 * G_STAGE;
        const uint32_t sb = sa + G_STAGE;
        if (c + 1 < NCHUNK) {
            const int st2 = (c + 1) & 1;
            gemm_prefetch(A, B, m0, n0, c + 1, sbase + st2 * 2 * G_STAGE,
                          sbase + st2 * 2 * G_STAGE + G_STAGE, tid);
            CP_COMMIT();
            CP_WAIT1();
        } else {
            CP_WAIT0();
        }
        __syncthreads();

#pragma unroll
        for (int ks = 0; ks < 4; ks++) {
            uint32_t af[4][4];
#pragma unroll
            for (int i = 0; i < 4; i++) {
                int r = wm * 64 + i * 16 + (quad & 1) * 8 + l8;
                int kof = ks * 16 + (quad >> 1) * 8;
                ldsm4(sa + r * G_STRIDE + kof * 2,
                      af[i][0], af[i][1], af[i][2], af[i][3]);
            }
            uint32_t bfr[2][4];
#pragma unroll
            for (int p = 0; p < 2; p++) {
                int nr = wn * 32 + p * 16 + (quad >> 1) * 8 + l8;
                int kof = ks * 16 + (quad & 1) * 8;
                ldsm4(sb + nr * G_STRIDE + kof * 2,
                      bfr[p][0], bfr[p][1], bfr[p][2], bfr[p][3]);
            }
#pragma unroll
            for (int i = 0; i < 4; i++)
#pragma unroll
                for (int p = 0; p < 2; p++) {
                    mma16816(acc[i][2 * p], af[i][0], af[i][1], af[i][2], af[i][3],
                             bfr[p][0], bfr[p][1]);
                    mma16816(acc[i][2 * p + 1], af[i][0], af[i][1], af[i][2], af[i][3],
                             bfr[p][2], bfr[p][3]);
                }
        }
        __syncthreads();
    }

    // Epilogue
#pragma unroll
    for (int i = 0; i < 4; i++) {
        int r0 = m0 + wm * 64 + i * 16 + g;
        int r1 = r0 + 8;
#pragma unroll
        for (int j = 0; j < 4; j++) {
            int col = n0 + wn * 32 + j * 8 + 2 * cq;
            float v0 = acc[i][j][0], v1 = acc[i][j][1];
            float v2 = acc[i][j][2], v3 = acc[i][j][3];
            if (EPI == 1) {
                float b0 = bias[col], b1 = bias[col + 1];
                *(float2*)(Cf + (size_t)r0 * 1024 + col) = make_float2(v0 + b0, v1 + b1);
                *(float2*)(Cf + (size_t)r1 * 1024 + col) = make_float2(v2 + b0, v3 + b1);
            } else {
                int head = col >> 6, dk = col & 63;
                size_t o0 = (size_t)r0 * 2048 + head * 128 + dk;
                size_t o1 = (size_t)r1 * 2048 + head * 128 + dk;
                bf16 h0 = __float2bfloat16_rn(v0), h1 = __float2bfloat16_rn(v1);
                bf16 h2 = __float2bfloat16_rn(v2), h3 = __float2bfloat16_rn(v3);
                *(uint32_t*)(Cb + o0) = packbf(__bfloat162float(h0), __bfloat162float(h1));
                *(uint32_t*)(Cb + o0 + 64) = packbf(v0 - __bfloat162float(h0),
                                                    v1 - __bfloat162float(h1));
                *(uint32_t*)(Cb + o1) = packbf(__bfloat162float(h2), __bfloat162float(h3));
                *(uint32_t*)(Cb + o1 + 64) = packbf(v2 - __bfloat162float(h2),
                                                    v3 - __bfloat162float(h3));
            }
        }
    }
}

// ---------------------------------------------------------------------------
// Tensor-core flash attention.
// Grid (32 qblocks, 32 bh). CTA = 128 thr = 4 warps; warp owns 16 query rows.
// BLOCK_M = 64, KV tile = 64 keys. QK^T: 12 k-steps (qh*kh, ql*kh, qh*kl).
// PV: 3 terms (ph*vh, ph*vl, pl*vh), V frags via ldmatrix.trans.
// Output: ctx hi/lo bf16 into CS row-concat layout [ch(1024) | cl(1024)].
// ---------------------------------------------------------------------------
#define A_STRIDE 272                 // bytes per key row (128 halves + pad)
#define A_TILE   (64 * A_STRIDE)     // 17408
#define A_STAGE  (2 * A_TILE)        // K + V = 34816
#define A_PAD_OFF (2 * A_STAGE)      // 69632
#define A_SMEM   (A_PAD_OFF + 512)   // 70144

__device__ __forceinline__ void attn_prefetch(const bf16* KS, const bf16* VS,
                                              const int* amask, char* smem,
                                              uint32_t sbase, int b, int h,
                                              int kt, int st, int tid) {
    const uint32_t kb = sbase + st * A_STAGE;
    const uint32_t vb = kb + A_TILE;
    const bf16* ksrc = KS + ((size_t)(b * NSEQ + kt)) * 2048 + h * 128;
    const bf16* vsrc = VS + ((size_t)(b * NSEQ + kt)) * 2048 + h * 128;
#pragma unroll
    for (int it = 0; it < 8; it++) {
        int idx = tid + it * 128;
        int row = idx >> 4, seg = idx & 15;
        CP16(kb + row * A_STRIDE + seg * 16, ksrc + (size_t)row * 2048 + seg * 8);
    }
#pragma unroll
    for (int it = 0; it < 8; it++) {
        int idx = tid + it * 128;
        int row = idx >> 4, seg = idx & 15;
        CP16(vb + row * A_STRIDE + seg * 16, vsrc + (size_t)row * 2048 + seg * 8);
    }
    if (tid < 64) {
        float pv = amask[b * NSEQ + kt + tid] ? 0.0f : -1e30f;
        *(float*)(smem + A_PAD_OFF + st * 256 + tid * 4) = pv;
    }
}

__global__ __launch_bounds__(128)
void attn_mma(const bf16* __restrict__ QS, const bf16* __restrict__ KS,
              const bf16* __restrict__ VS, const int* __restrict__ amask,
              bf16* __restrict__ CS) {
    extern __shared__ char smem[];
    const uint32_t sbase = smem_u32(smem);
    const int tid = threadIdx.x;
    const int w = tid >> 5, L = tid & 31;
    const int g = L >> 2, cq = L & 3;
    const int quad = L >> 3, l8 = L & 7;
    const int qb = 31 - blockIdx.x;          // big blocks first
    const int m0 = qb * 64;
    const int bh = blockIdx.y;
    const int b = bh >> 4, h = bh & 15;
    const int rowA = m0 + w * 16 + g;
    const int rowB = rowA + 8;

    // Q fragments: qa[0..3] = qh k-steps, qa[4..7] = ql k-steps
    uint32_t qa[8][4];
    {
        const bf16* qA = QS + (size_t)(b * NSEQ + rowA) * 2048 + h * 128;
        const bf16* qB = QS + (size_t)(b * NSEQ + rowB) * 2048 + h * 128;
#pragma unroll
        for (int s = 0; s < 8; s++) {
            qa[s][0] = *(const uint32_t*)(qA + s * 16 + 2 * cq);
            qa[s][1] = *(const uint32_t*)(qB + s * 16 + 2 * cq);
            qa[s][2] = *(const uint32_t*)(qA + s * 16 + 2 * cq + 8);
            qa[s][3] = *(const uint32_t*)(qB + s * 16 + 2 * cq + 8);
        }
    }

    float co[8][4];
#pragma unroll
    for (int d = 0; d < 8; d++)
#pragma unroll
        for (int k = 0; k < 4; k++) co[d][k] = 0.0f;
    float mx0 = -1e30f, mx1 = -1e30f;
    float l0 = 0.0f, l1 = 0.0f;

    const int nt = qb + 1;
    attn_prefetch(KS, VS, amask, smem, sbase, b, h, 0, 0, tid);
    CP_COMMIT();

    for (int t = 0; t < nt; t++) {
        const int kt = t * 64;
        const int st = t & 1;
        if (t + 1 < nt) {
            attn_prefetch(KS, VS, amask, smem, sbase, b, h, (t + 1) * 64,
                          (t + 1) & 1, tid);
            CP_COMMIT();
            CP_WAIT1();
        } else {
            CP_WAIT0();
        }
        __syncthreads();

        const uint32_t kb = sbase + st * A_STAGE;
        const uint32_t vb = kb + A_TILE;
        const float* padf = (const float*)(smem + A_PAD_OFF + st * 256);

        // ---- scores: 12 k-steps (qh*kh, ql*kh, qh*kl) ----
        float sc[8][4];
#pragma unroll
        for (int f = 0; f < 8; f++)
#pragma unroll
            for (int k = 0; k < 4; k++) sc[f][k] = 0.0f;

#pragma unroll
        for (int ks = 0; ks < 12; ks++) {
            const int qi = (ks < 8) ? ks : (ks - 8);
            const int koff = (ks < 4) ? ks * 16
                              : (ks < 8 ? (ks - 4) * 16 : 64 + (ks - 8) * 16);
#pragma unroll
            for (int p = 0; p < 4; p++) {
                uint32_t b0, b1, b2, b3;
                int krow = p * 16 + (quad >> 1) * 8 + l8;
                int kof = koff + (quad & 1) * 8;
                ldsm4(kb + krow * A_STRIDE + kof * 2, b0, b1, b2, b3);
                mma16816(sc[2 * p], qa[qi][0], qa[qi][1], qa[qi][2], qa[qi][3], b0, b1);
                mma16816(sc[2 * p + 1], qa[qi][0], qa[qi][1], qa[qi][2], qa[qi][3], b2, b3);
            }
        }

        // ---- mask + scale + row max ----
        const bool diag = (kt == m0);
        float mn0 = mx0, mn1 = mx1;
#pragma unroll
        for (int f = 0; f < 8; f++) {
            float2 pd = *(const float2*)(padf + f * 8 + 2 * cq);
            int k0 = kt + f * 8 + 2 * cq;
            float s0 = sc[f][0] * 0.125f + pd.x;
            float s1 = sc[f][1] * 0.125f + pd.y;
            float s2 = sc[f][2] * 0.125f + pd.x;
            float s3 = sc[f][3] * 0.125f + pd.y;
            if (diag) {
                if (k0 > rowA) s0 = -1e30f;
                if (k0 + 1 > rowA) s1 = -1e30f;
                if (k0 > rowB) s2 = -1e30f;
                if (k0 + 1 > rowB) s3 = -1e30f;
            }
            sc[f][0] = s0; sc[f][1] = s1; sc[f][2] = s2; sc[f][3] = s3;
            mn0 = fmaxf(mn0, fmaxf(s0, s1));
            mn1 = fmaxf(mn1, fmaxf(s2, s3));
        }
        mn0 = fmaxf(mn0, __shfl_xor_sync(0xffffffffu, mn0, 1));
        mn0 = fmaxf(mn0, __shfl_xor_sync(0xffffffffu, mn0, 2));
        mn1 = fmaxf(mn1, __shfl_xor_sync(0xffffffffu, mn1, 1));
        mn1 = fmaxf(mn1, __shfl_xor_sync(0xffffffffu, mn1, 2));

        const float corr0 = __expf(mx0 - mn0);
        const float corr1 = __expf(mx1 - mn1);
        mx0 = mn0; mx1 = mn1;
        l0 *= corr0; l1 *= corr1;
#pragma unroll
        for (int d = 0; d < 8; d++) {
            co[d][0] *= corr0; co[d][1] *= corr0;
            co[d][2] *= corr1; co[d][3] *= corr1;
        }

        // ---- exp + P hi/lo fragments ----
        uint32_t phA[8], phB[8], plA[8], plB[8];
#pragma unroll
        for (int f = 0; f < 8; f++) {
            float p0 = __expf(sc[f][0] - mn0), p1 = __expf(sc[f][1] - mn0);
            float p2 = __expf(sc[f][2] - mn1), p3 = __expf(sc[f][3] - mn1);
            l0 += p0 + p1; l1 += p2 + p3;
            bf16 h0 = __float2bfloat16_rn(p0), h1 = __float2bfloat16_rn(p1);
            bf16 h2 = __float2bfloat16_rn(p2), h3 = __float2bfloat16_rn(p3);
            phA[f] = packbf(__bfloat162float(h0), __bfloat162float(h1));
            phB[f] = packbf(__bfloat162float(h2), __bfloat162float(h3));
            plA[f] = packbf(p0 - __bfloat162float(h0), p1 - __bfloat162float(h1));
            plB[f] = packbf(p2 - __bfloat162float(h2), p3 - __bfloat162float(h3));
        }

        // ---- O += P @ V (3 terms) ----
#pragma unroll
        for (int kk = 0; kk < 4; kk++) {
            uint32_t a0 = phA[2 * kk], a1 = phB[2 * kk];
            uint32_t a2 = phA[2 * kk + 1], a3 = phB[2 * kk + 1];
            uint32_t la0 = plA[2 * kk], la1 = plB[2 * kk];
            uint32_t la2 = plA[2 * kk + 1], la3 = plB[2 * kk + 1];
#pragma unroll
            for (int dp = 0; dp < 4; dp++) {
                int key = kk * 16 + (quad & 1) * 8 + l8;
                int dkc = (2 * dp + (quad >> 1)) * 8;
                uint32_t vh0, vh1, vh2, vh3, vl0, vl1, vl2, vl3;
                ldsm4t(vb + key * A_STRIDE + dkc * 2, vh0, vh1, vh2, vh3);
                ldsm4t(vb + key * A_STRIDE + 128 + dkc * 2, vl0, vl1, vl2, vl3);
                mma16816(co[2 * dp],     a0, a1, a2, a3, vh0, vh1);
                mma16816(co[2 * dp + 1], a0, a1, a2, a3, vh2, vh3);
                mma16816(co[2 * dp],     a0, a1, a2, a3, vl0, vl1);
                mma16816(co[2 * dp + 1], a0, a1, a2, a3, vl2, vl3);
                mma16816(co[2 * dp],     la0, la1, la2, la3, vh0, vh1);
                mma16816(co[2 * dp + 1], la0, la1, la2, la3, vh2, vh3);
            }
        }
        __syncthreads();
    }

    // ---- finalize: reduce l across lane group, normalize, write hi/lo ----
    l0 += __shfl_xor_sync(0xffffffffu, l0, 1);
    l0 += __shfl_xor_sync(0xffffffffu, l0, 2);
    l1 += __shfl_xor_sync(0xffffffffu, l1, 1);
    l1 += __shfl_xor_sync(0xffffffffu, l1, 2);
    const float inv0 = 1.0f / l0, inv1 = 1.0f / l1;

#pragma unroll
    for (int d = 0; d < 8; d++) {
        int dk = d * 8 + 2 * cq;
        size_t bA = (size_t)(b * NSEQ + rowA) * 2048 + h * 64 + dk;
        size_t bB = (size_t)(b * NSEQ + rowB) * 2048 + h * 64 + dk;
        float v0 = co[d][0] * inv0, v1 = co[d][1] * inv0;
        float v2 = co[d][2] * inv1, v3 = co[d][3] * inv1;
        bf16 h0 = __float2bfloat16_rn(v0), h1 = __float2bfloat16_rn(v1);
        bf16 h2 = __float2bfloat16_rn(v2), h3 = __float2bfloat16_rn(v3);
        *(uint32_t*)(CS + bA) = packbf(__bfloat162float(h0), __bfloat162float(h1));
        *(uint32_t*)(CS + bA + 1024) = packbf(v0 - __bfloat162float(h0),
                                              v1 - __bfloat162float(h1));
        *(uint32_t*)(CS + bB) = packbf(__bfloat162float(h2), __bfloat162float(h3));
        *(uint32_t*)(CS + bB + 1024) = packbf(v2 - __bfloat162float(h2),
                                              v3 - __bfloat162float(h3));
    }
}

// ---------------------------------------------------------------------------
// Launch
// ---------------------------------------------------------------------------
extern "C" void kernel_launch(void* const* d_in, const int* in_sizes, int n_in,
                              void* d_out, int out_size) {
    const float* x     = (const float*)d_in[0];
    const int*   amask = (const int*)d_in[1];
    const float* W_Q   = (const float*)d_in[2];
    const float* W_K   = (const float*)d_in[3];
    const float* W_V   = (const float*)d_in[4];
    const float* W_out = (const float*)d_in[5];
    const float* b_out = (const float*)d_in[6];
    float* out = (float*)d_out;

    bf16 *xs, *wqs, *wks, *wvs, *wos, *qs, *ks, *vs, *cs;
    cudaGetSymbolAddress((void**)&xs, g_xs);
    cudaGetSymbolAddress((void**)&wqs, g_wqs);
    cudaGetSymbolAddress((void**)&wks, g_wks);
    cudaGetSymbolAddress((void**)&wvs, g_wvs);
    cudaGetSymbolAddress((void**)&wos, g_wos);
    cudaGetSymbolAddress((void**)&qs, g_qs);
    cudaGetSymbolAddress((void**)&ks, g_ks);
    cudaGetSymbolAddress((void**)&vs, g_vs);
    cudaGetSymbolAddress((void**)&cs, g_cs);

    cudaFuncSetAttribute(mma_gemm<0>, cudaFuncAttributeMaxDynamicSharedMemorySize, G_SMEM);
    cudaFuncSetAttribute(mma_gemm<1>, cudaFuncAttributeMaxDynamicSharedMemorySize, G_SMEM);
    cudaFuncSetAttribute(attn_mma, cudaFuncAttributeMaxDynamicSharedMemorySize, A_SMEM);

    const int nx4 = MROWS * DMODEL / 4;
    const int nw4 = DMODEL * DMODEL / 4;
    split_kernel<<<(nx4 + 255) / 256, 256>>>(x, xs, nx4);
    split_kernel<<<(nw4 + 255) / 256, 256>>>(W_Q, wqs, nw4);
    split_kernel<<<(nw4 + 255) / 256, 256>>>(W_K, wks, nw4);
    split_kernel<<<(nw4 + 255) / 256, 256>>>(W_V, wvs, nw4);
    split_kernel<<<(nw4 + 255) / 256, 256>>>(W_out, wos, nw4);

    dim3 ggrid(DMODEL / 128, MROWS / 128);   // (8, 32)
    mma_gemm<0><<<ggrid, 256, G_SMEM>>>(xs, wqs, nullptr, qs, nullptr);
    mma_gemm<0><<<ggrid, 256, G_SMEM>>>(xs, wks, nullptr, ks, nullptr);
    mma_gemm<0><<<ggrid, 256, G_SMEM>>>(xs, wvs, nullptr, vs, nullptr);

    dim3 agrid(NSEQ / 64, BATCH * NHEAD);    // (32, 32)
    attn_mma<<<agrid, 128, A_SMEM>>>(qs, ks, vs, amask, cs);

    mma_gemm<1><<<ggrid, 256, G_SMEM>>>(cs, wos, out, nullptr, b_out);
}

// round 7
// speedup vs baseline: 5.1880x; 1.0835x over previous
#include <cuda_runtime.h>
#include <cuda_bf16.h>
#include <cstdint>

// Problem constants
#define BATCH 2
#define NSEQ  2048
#define DMODEL 1024
#define NHEAD 16
#define DK    64
#define MROWS (BATCH * NSEQ)   // 4096

typedef __nv_bfloat16 bf16;

// ---------------------------------------------------------------------------
// Scratch (allocation-free rule: __device__ globals)
// Split arrays: [rows][2048] = [hi(1024) | lo(1024)]
// Q/K/V arrays: per-head concat: [rows][2048], head h at cols h*128:
//   hi dk 0..63 then lo dk 0..63.
// g_wqkv: concatenated [Wq;Wk;Wv] = [3072][2048] split.
// ---------------------------------------------------------------------------
__device__ bf16 g_xs  [MROWS * 2048];
__device__ bf16 g_wqkv[3 * DMODEL * 2048];
__device__ bf16 g_wos [DMODEL * 2048];
__device__ bf16 g_qs  [MROWS * 2048];
__device__ bf16 g_ks  [MROWS * 2048];
__device__ bf16 g_vs  [MROWS * 2048];
__device__ bf16 g_cs  [MROWS * 2048];

// ---------------------------------------------------------------------------
// PTX helpers (base compute_103 features only)
// ---------------------------------------------------------------------------
__device__ __forceinline__ uint32_t smem_u32(const void* p) {
    uint32_t a;
    asm("{ .reg .u64 t; cvta.to.shared.u64 t, %1; cvt.u32.u64 %0, t; }"
        : "=r"(a) : "l"(p));
    return a;
}
#define CP16(dst, src) \
    asm volatile("cp.async.cg.shared.global [%0], [%1], 16;" \
                 :: "r"(dst), "l"(src))
#define CP_COMMIT() asm volatile("cp.async.commit_group;" ::: "memory")
#define CP_WAIT0()  asm volatile("cp.async.wait_group 0;" ::: "memory")
#define CP_WAIT1()  asm volatile("cp.async.wait_group 1;" ::: "memory")

__device__ __forceinline__ void ldsm4(uint32_t addr, uint32_t& r0, uint32_t& r1,
                                      uint32_t& r2, uint32_t& r3) {
    asm volatile("ldmatrix.sync.aligned.m8n8.x4.shared.b16 {%0,%1,%2,%3}, [%4];"
                 : "=r"(r0), "=r"(r1), "=r"(r2), "=r"(r3) : "r"(addr));
}
__device__ __forceinline__ void ldsm4t(uint32_t addr, uint32_t& r0, uint32_t& r1,
                                       uint32_t& r2, uint32_t& r3) {
    asm volatile("ldmatrix.sync.aligned.m8n8.x4.trans.shared.b16 {%0,%1,%2,%3}, [%4];"
                 : "=r"(r0), "=r"(r1), "=r"(r2), "=r"(r3) : "r"(addr));
}
// D += A*B  (m16n8k16, bf16 in, fp32 accum)
__device__ __forceinline__ void mma16816(float* c, uint32_t a0, uint32_t a1,
                                         uint32_t a2, uint32_t a3,
                                         uint32_t b0, uint32_t b1) {
    asm volatile(
        "mma.sync.aligned.m16n8k16.row.col.f32.bf16.bf16.f32 "
        "{%0,%1,%2,%3}, {%4,%5,%6,%7}, {%8,%9}, {%0,%1,%2,%3};"
        : "+f"(c[0]), "+f"(c[1]), "+f"(c[2]), "+f"(c[3])
        : "r"(a0), "r"(a1), "r"(a2), "r"(a3), "r"(b0), "r"(b1));
}
__device__ __forceinline__ uint32_t packbf(float a, float b) {
    __nv_bfloat162 t = __floats2bfloat162_rn(a, b);
    return *(uint32_t*)&t;
}

// ---------------------------------------------------------------------------
// fp32 [R][1024] -> bf16 [R][2048] = [hi | lo]
// ---------------------------------------------------------------------------
__device__ __forceinline__ void split_body(const float* __restrict__ in,
                                           bf16* __restrict__ out, int i) {
    float4 v = ((const float4*)in)[i];
    int r = i >> 8;
    int c = (i & 255) * 4;
    bf16 h0 = __float2bfloat16_rn(v.x), h1 = __float2bfloat16_rn(v.y);
    bf16 h2 = __float2bfloat16_rn(v.z), h3 = __float2bfloat16_rn(v.w);
    uint32_t* oh = (uint32_t*)(out + (size_t)r * 2048 + c);
    uint32_t* ol = (uint32_t*)(out + (size_t)r * 2048 + 1024 + c);
    oh[0] = packbf(__bfloat162float(h0), __bfloat162float(h1));
    oh[1] = packbf(__bfloat162float(h2), __bfloat162float(h3));
    ol[0] = packbf(v.x - __bfloat162float(h0), v.y - __bfloat162float(h1));
    ol[1] = packbf(v.z - __bfloat162float(h2), v.w - __bfloat162float(h3));
}

__global__ __launch_bounds__(256)
void split_kernel(const float* __restrict__ in, bf16* __restrict__ out, int n4) {
    int i = blockIdx.x * blockDim.x + threadIdx.x;
    if (i >= n4) return;
    split_body(in, out, i);
}

// Batched split of the 4 weight matrices (blockIdx.y selects matrix)
__global__ __launch_bounds__(256)
void split_w4(const float* __restrict__ w0, const float* __restrict__ w1,
              const float* __restrict__ w2, const float* __restrict__ w3,
              bf16* __restrict__ wqkv, bf16* __restrict__ wos, int n4) {
    int i = blockIdx.x * blockDim.x + threadIdx.x;
    if (i >= n4) return;
    int y = blockIdx.y;
    const float* src = (y == 0) ? w0 : (y == 1) ? w1 : (y == 2) ? w2 : w3;
    bf16* dst = (y < 3) ? wqkv + (size_t)y * DMODEL * 2048 : wos;
    split_body(src, dst, i);
}

// ---------------------------------------------------------------------------
// Tensor-core GEMM: C[m][n] = sum over fp32-split 3-term concat (K'=3072)
//   chunks c: 0-15 -> Ah*Bh, 16-31 -> Al*Bh, 32-47 -> Ah*Bl
// A: [4096][2048] split, B: [NB][2048] split (NB = 3072 fused QKV or 1024).
// CTA tile 128(M) x 256(N), 256 thr, 8 warps (2x4), warp tile 64x64.
// 3-stage cp.async ring, one __syncthreads per chunk.
// EPI 0: bf16 per-head concat out to q/k/v (selected by n). EPI 1: fp32+bias.
// ---------------------------------------------------------------------------
#define G_STRIDE 144                    // bytes per smem row (128B data + pad)
#define G_ASTG   (128 * G_STRIDE)       // 18432
#define G_BSTG   (256 * G_STRIDE)       // 36864
#define G_STAGE  (G_ASTG + G_BSTG)      // 55296
#define G_SMEM   (3 * G_STAGE)          // 165888
#define NCHUNK 48

__device__ __forceinline__ void gemm_prefetch(const bf16* A, const bf16* B,
                                              int m0, int n0, int c,
                                              uint32_t stg, int tid) {
    int ac = (c < 32) ? c * 64 : (c - 32) * 64;
    int bc = (c < 16) ? c * 64 : (c < 32 ? (c - 16) * 64 : (c - 32) * 64 + 1024);
    const uint32_t sa = stg;
    const uint32_t sb = stg + G_ASTG;
#pragma unroll
    for (int it = 0; it < 4; it++) {
        int idx = tid + it * 256;
        int row = idx >> 3, seg = idx & 7;
        CP16(sa + row * G_STRIDE + seg * 16,
             A + (size_t)(m0 + row) * 2048 + ac + seg * 8);
    }
#pragma unroll
    for (int it = 0; it < 8; it++) {
        int idx = tid + it * 256;
        int row = idx >> 3, seg = idx & 7;
        CP16(sb + row * G_STRIDE + seg * 16,
             B + (size_t)(n0 + row) * 2048 + bc + seg * 8);
    }
}

template <int EPI>
__global__ __launch_bounds__(256, 1)
void mma_gemm(const bf16* __restrict__ A, const bf16* __restrict__ B,
              float* __restrict__ Cf,
              bf16* __restrict__ Cq, bf16* __restrict__ Ck, bf16* __restrict__ Cv,
              const float* __restrict__ bias) {
    extern __shared__ char smem[];
    const uint32_t sbase = smem_u32(smem);
    const int tid = threadIdx.x;
    const int w = tid >> 5, L = tid & 31;
    const int g = L >> 2, cq = L & 3;
    const int wm = w >> 2, wn = w & 3;
    const int m0 = blockIdx.y * 128, n0 = blockIdx.x * 256;
    const int quad = L >> 3, l8 = L & 7;

    float acc[4][8][4];
#pragma unroll
    for (int i = 0; i < 4; i++)
#pragma unroll
        for (int j = 0; j < 8; j++)
#pragma unroll
            for (int k = 0; k < 4; k++) acc[i][j][k] = 0.0f;

    gemm_prefetch(A, B, m0, n0, 0, sbase, tid);
    CP_COMMIT();
    gemm_prefetch(A, B, m0, n0, 1, sbase + G_STAGE, tid);
    CP_COMMIT();

    int stage = 0;
    for (int c = 0; c < NCHUNK; c++) {
        if (c == NCHUNK - 1) { CP_WAIT0(); } else { CP_WAIT1(); }
        __syncthreads();
        if (c + 2 < NCHUNK) {
            int s2 = stage + 2; if (s2 >= 3) s2 -= 3;
            gemm_prefetch(A, B, m0, n0, c + 2, sbase + s2 * G_STAGE, tid);
            CP_COMMIT();
        }
        const uint32_t sa = sbase + stage * G_STAGE;
        const uint32_t sb = sa + G_ASTG;

#pragma unroll
        for (int ks = 0; ks < 4; ks++) {
            uint32_t af[4][4];
#pragma unroll
            for (int i = 0; i < 4; i++) {
                int r = wm * 64 + i * 16 + (quad & 1) * 8 + l8;
                int kof = ks * 16 + (quad >> 1) * 8;
                ldsm4(sa + r * G_STRIDE + kof * 2,
                      af[i][0], af[i][1], af[i][2], af[i][3]);
            }
            uint32_t bfr[4][4];
#pragma unroll
            for (int p = 0; p < 4; p++) {
                int nr = wn * 64 + p * 16 + (quad >> 1) * 8 + l8;
                int kof = ks * 16 + (quad & 1) * 8;
                ldsm4(sb + nr * G_STRIDE + kof * 2,
                      bfr[p][0], bfr[p][1], bfr[p][2], bfr[p][3]);
            }
#pragma unroll
            for (int i = 0; i < 4; i++)
#pragma unroll
                for (int p = 0; p < 4; p++) {
                    mma16816(acc[i][2 * p], af[i][0], af[i][1], af[i][2], af[i][3],
                             bfr[p][0], bfr[p][1]);
                    mma16816(acc[i][2 * p + 1], af[i][0], af[i][1], af[i][2], af[i][3],
                             bfr[p][2], bfr[p][3]);
                }
        }
        stage++; if (stage == 3) stage = 0;
    }

    // Epilogue
#pragma unroll
    for (int i = 0; i < 4; i++) {
        int r0 = m0 + wm * 64 + i * 16 + g;
        int r1 = r0 + 8;
#pragma unroll
        for (int j = 0; j < 8; j++) {
            int col = n0 + wn * 64 + j * 8 + 2 * cq;
            float v0 = acc[i][j][0], v1 = acc[i][j][1];
            float v2 = acc[i][j][2], v3 = acc[i][j][3];
            if (EPI == 1) {
                float b0 = bias[col], b1 = bias[col + 1];
                *(float2*)(Cf + (size_t)r0 * 1024 + col) = make_float2(v0 + b0, v1 + b1);
                *(float2*)(Cf + (size_t)r1 * 1024 + col) = make_float2(v2 + b0, v3 + b1);
            } else {
                int mat = col >> 10, cc = col & 1023;
                bf16* Cb = (mat == 0) ? Cq : (mat == 1) ? Ck : Cv;
                int head = cc >> 6, dk = cc & 63;
                size_t o0 = (size_t)r0 * 2048 + head * 128 + dk;
                size_t o1 = (size_t)r1 * 2048 + head * 128 + dk;
                bf16 h0 = __float2bfloat16_rn(v0), h1 = __float2bfloat16_rn(v1);
                bf16 h2 = __float2bfloat16_rn(v2), h3 = __float2bfloat16_rn(v3);
                *(uint32_t*)(Cb + o0) = packbf(__bfloat162float(h0), __bfloat162float(h1));
                *(uint32_t*)(Cb + o0 + 64) = packbf(v0 - __bfloat162float(h0),
                                                    v1 - __bfloat162float(h1));
                *(uint32_t*)(Cb + o1) = packbf(__bfloat162float(h2), __bfloat162float(h3));
                *(uint32_t*)(Cb + o1 + 64) = packbf(v2 - __bfloat162float(h2),
                                                    v3 - __bfloat162float(h3));
            }
        }
    }
}

// ---------------------------------------------------------------------------
// Tensor-core flash attention (one sync per tile, 2-stage cp.async).
// Grid (32 qblocks, 32 bh). CTA = 128 thr = 4 warps; warp owns 16 query rows.
// QK^T: 12 k-steps (qh*kh, ql*kh, qh*kl). PV: 3 terms, V via ldmatrix.trans.
// Output: ctx hi/lo bf16 into CS row-concat layout [ch(1024) | cl(1024)].
// ---------------------------------------------------------------------------
#define A_STRIDE 272                 // bytes per key row (128 halves + pad)
#define A_TILE   (64 * A_STRIDE)     // 17408
#define A_STAGE  (2 * A_TILE)        // K + V = 34816
#define A_PAD_OFF (2 * A_STAGE)      // 69632
#define A_SMEM   (A_PAD_OFF + 512)   // 70144

__device__ __forceinline__ void attn_prefetch(const bf16* KS, const bf16* VS,
                                              const int* amask, char* smem,
                                              uint32_t sbase, int b, int h,
                                              int kt, int st, int tid) {
    const uint32_t kb = sbase + st * A_STAGE;
    const uint32_t vb = kb + A_TILE;
    const bf16* ksrc = KS + ((size_t)(b * NSEQ + kt)) * 2048 + h * 128;
    const bf16* vsrc = VS + ((size_t)(b * NSEQ + kt)) * 2048 + h * 128;
#pragma unroll
    for (int it = 0; it < 8; it++) {
        int idx = tid + it * 128;
        int row = idx >> 4, seg = idx & 15;
        CP16(kb + row * A_STRIDE + seg * 16, ksrc + (size_t)row * 2048 + seg * 8);
    }
#pragma unroll
    for (int it = 0; it < 8; it++) {
        int idx = tid + it * 128;
        int row = idx >> 4, seg = idx & 15;
        CP16(vb + row * A_STRIDE + seg * 16, vsrc + (size_t)row * 2048 + seg * 8);
    }
    if (tid < 64) {
        float pv = amask[b * NSEQ + kt + tid] ? 0.0f : -1e30f;
        *(float*)(smem + A_PAD_OFF + st * 256 + tid * 4) = pv;
    }
}

__global__ __launch_bounds__(128)
void attn_mma(const bf16* __restrict__ QS, const bf16* __restrict__ KS,
              const bf16* __restrict__ VS, const int* __restrict__ amask,
              bf16* __restrict__ CS) {
    extern __shared__ char smem[];
    const uint32_t sbase = smem_u32(smem);
    const int tid = threadIdx.x;
    const int w = tid >> 5, L = tid & 31;
    const int g = L >> 2, cq = L & 3;
    const int quad = L >> 3, l8 = L & 7;
    const int qb = 31 - blockIdx.x;          // big blocks first
    const int m0 = qb * 64;
    const int bh = blockIdx.y;
    const int b = bh >> 4, h = bh & 15;
    const int rowA = m0 + w * 16 + g;
    const int rowB = rowA + 8;

    // Q fragments: qa[0..3] = qh k-steps, qa[4..7] = ql k-steps
    uint32_t qa[8][4];
    {
        const bf16* qA = QS + (size_t)(b * NSEQ + rowA) * 2048 + h * 128;
        const bf16* qB = QS + (size_t)(b * NSEQ + rowB) * 2048 + h * 128;
#pragma unroll
        for (int s = 0; s < 8; s++) {
            qa[s][0] = *(const uint32_t*)(qA + s * 16 + 2 * cq);
            qa[s][1] = *(const uint32_t*)(qB + s * 16 + 2 * cq);
            qa[s][2] = *(const uint32_t*)(qA + s * 16 + 2 * cq + 8);
            qa[s][3] = *(const uint32_t*)(qB + s * 16 + 2 * cq + 8);
        }
    }

    float co[8][4];
#pragma unroll
    for (int d = 0; d < 8; d++)
#pragma unroll
        for (int k = 0; k < 4; k++) co[d][k] = 0.0f;
    float mx0 = -1e30f, mx1 = -1e30f;
    float l0 = 0.0f, l1 = 0.0f;

    const int nt = qb + 1;
    attn_prefetch(KS, VS, amask, smem, sbase, b, h, 0, 0, tid);
    CP_COMMIT();

    for (int t = 0; t < nt; t++) {
        const int kt = t * 64;
        const int st = t & 1;
        CP_WAIT0();
        __syncthreads();
        if (t + 1 < nt) {
            attn_prefetch(KS, VS, amask, smem, sbase, b, h, (t + 1) * 64,
                          (t + 1) & 1, tid);
            CP_COMMIT();
        }

        const uint32_t kb = sbase + st * A_STAGE;
        const uint32_t vb = kb + A_TILE;
        const float* padf = (const float*)(smem + A_PAD_OFF + st * 256);

        // ---- scores: 12 k-steps (qh*kh, ql*kh, qh*kl) ----
        float sc[8][4];
#pragma unroll
        for (int f = 0; f < 8; f++)
#pragma unroll
            for (int k = 0; k < 4; k++) sc[f][k] = 0.0f;

#pragma unroll
        for (int ks = 0; ks < 12; ks++) {
            const int qi = (ks < 8) ? ks : (ks - 8);
            const int koff = (ks < 4) ? ks * 16
                              : (ks < 8 ? (ks - 4) * 16 : 64 + (ks - 8) * 16);
#pragma unroll
            for (int p = 0; p < 4; p++) {
                uint32_t b0, b1, b2, b3;
                int krow = p * 16 + (quad >> 1) * 8 + l8;
                int kof = koff + (quad & 1) * 8;
                ldsm4(kb + krow * A_STRIDE + kof * 2, b0, b1, b2, b3);
                mma16816(sc[2 * p], qa[qi][0], qa[qi][1], qa[qi][2], qa[qi][3], b0, b1);
                mma16816(sc[2 * p + 1], qa[qi][0], qa[qi][1], qa[qi][2], qa[qi][3], b2, b3);
            }
        }

        // ---- mask + scale + row max ----
        const bool diag = (kt == m0);
        float mn0 = mx0, mn1 = mx1;
#pragma unroll
        for (int f = 0; f < 8; f++) {
            float2 pd = *(const float2*)(padf + f * 8 + 2 * cq);
            int k0 = kt + f * 8 + 2 * cq;
            float s0 = sc[f][0] * 0.125f + pd.x;
            float s1 = sc[f][1] * 0.125f + pd.y;
            float s2 = sc[f][2] * 0.125f + pd.x;
            float s3 = sc[f][3] * 0.125f + pd.y;
            if (diag) {
                if (k0 > rowA) s0 = -1e30f;
                if (k0 + 1 > rowA) s1 = -1e30f;
                if (k0 > rowB) s2 = -1e30f;
                if (k0 + 1 > rowB) s3 = -1e30f;
            }
            sc[f][0] = s0; sc[f][1] = s1; sc[f][2] = s2; sc[f][3] = s3;
            mn0 = fmaxf(mn0, fmaxf(s0, s1));
            mn1 = fmaxf(mn1, fmaxf(s2, s3));
        }
        mn0 = fmaxf(mn0, __shfl_xor_sync(0xffffffffu, mn0, 1));
        mn0 = fmaxf(mn0, __shfl_xor_sync(0xffffffffu, mn0, 2));
        mn1 = fmaxf(mn1, __shfl_xor_sync(0xffffffffu, mn1, 1));
        mn1 = fmaxf(mn1, __shfl_xor_sync(0xffffffffu, mn1, 2));

        const float corr0 = __expf(mx0 - mn0);
        const float corr1 = __expf(mx1 - mn1);
        mx0 = mn0; mx1 = mn1;
        l0 *= corr0; l1 *= corr1;
#pragma unroll
        for (int d = 0; d < 8; d++) {
            co[d][0] *= corr0; co[d][1] *= corr0;
            co[d][2] *= corr1; co[d][3] *= corr1;
        }

        // ---- exp + P hi/lo fragments ----
        uint32_t phA[8], phB[8], plA[8], plB[8];
#pragma unroll
        for (int f = 0; f < 8; f++) {
            float p0 = __expf(sc[f][0] - mn0), p1 = __expf(sc[f][1] - mn0);
            float p2 = __expf(sc[f][2] - mn1), p3 = __expf(sc[f][3] - mn1);
            l0 += p0 + p1; l1 += p2 + p3;
            bf16 h0 = __float2bfloat16_rn(p0), h1 = __float2bfloat16_rn(p1);
            bf16 h2 = __float2bfloat16_rn(p2), h3 = __float2bfloat16_rn(p3);
            phA[f] = packbf(__bfloat162float(h0), __bfloat162float(h1));
            phB[f] = packbf(__bfloat162float(h2), __bfloat162float(h3));
            plA[f] = packbf(p0 - __bfloat162float(h0), p1 - __bfloat162float(h1));
            plB[f] = packbf(p2 - __bfloat162float(h2), p3 - __bfloat162float(h3));
        }

        // ---- O += P @ V (3 terms) ----
#pragma unroll
        for (int kk = 0; kk < 4; kk++) {
            uint32_t a0 = phA[2 * kk], a1 = phB[2 * kk];
            uint32_t a2 = phA[2 * kk + 1], a3 = phB[2 * kk + 1];
            uint32_t la0 = plA[2 * kk], la1 = plB[2 * kk];
            uint32_t la2 = plA[2 * kk + 1], la3 = plB[2 * kk + 1];
#pragma unroll
            for (int dp = 0; dp < 4; dp++) {
                int key = kk * 16 + (quad & 1) * 8 + l8;
                int dkc = (2 * dp + (quad >> 1)) * 8;
                uint32_t vh0, vh1, vh2, vh3, vl0, vl1, vl2, vl3;
                ldsm4t(vb + key * A_STRIDE + dkc * 2, vh0, vh1, vh2, vh3);
                ldsm4t(vb + key * A_STRIDE + 128 + dkc * 2, vl0, vl1, vl2, vl3);
                mma16816(co[2 * dp],     a0, a1, a2, a3, vh0, vh1);
                mma16816(co[2 * dp + 1], a0, a1, a2, a3, vh2, vh3);
                mma16816(co[2 * dp],     a0, a1, a2, a3, vl0, vl1);
                mma16816(co[2 * dp + 1], a0, a1, a2, a3, vl2, vl3);
                mma16816(co[2 * dp],     la0, la1, la2, la3, vh0, vh1);
                mma16816(co[2 * dp + 1], la0, la1, la2, la3, vh2, vh3);
            }
        }
    }

    // ---- finalize ----
    l0 += __shfl_xor_sync(0xffffffffu, l0, 1);
    l0 += __shfl_xor_sync(0xffffffffu, l0, 2);
    l1 += __shfl_xor_sync(0xffffffffu, l1, 1);
    l1 += __shfl_xor_sync(0xffffffffu, l1, 2);
    const float inv0 = 1.0f / l0, inv1 = 1.0f / l1;

#pragma unroll
    for (int d = 0; d < 8; d++) {
        int dk = d * 8 + 2 * cq;
        size_t bA = (size_t)(b * NSEQ + rowA) * 2048 + h * 64 + dk;
        size_t bB = (size_t)(b * NSEQ + rowB) * 2048 + h * 64 + dk;
        float v0 = co[d][0] * inv0, v1 = co[d][1] * inv0;
        float v2 = co[d][2] * inv1, v3 = co[d][3] * inv1;
        bf16 h0 = __float2bfloat16_rn(v0), h1 = __float2bfloat16_rn(v1);
        bf16 h2 = __float2bfloat16_rn(v2), h3 = __float2bfloat16_rn(v3);
        *(uint32_t*)(CS + bA) = packbf(__bfloat162float(h0), __bfloat162float(h1));
        *(uint32_t*)(CS + bA + 1024) = packbf(v0 - __bfloat162float(h0),
                                              v1 - __bfloat162float(h1));
        *(uint32_t*)(CS + bB) = packbf(__bfloat162float(h2), __bfloat162float(h3));
        *(uint32_t*)(CS + bB + 1024) = packbf(v2 - __bfloat162float(h2),
                                              v3 - __bfloat162float(h3));
    }
}

// ---------------------------------------------------------------------------
// Launch
// ---------------------------------------------------------------------------
extern "C" void kernel_launch(void* const* d_in, const int* in_sizes, int n_in,
                              void* d_out, int out_size) {
    const float* x     = (const float*)d_in[0];
    const int*   amask = (const int*)d_in[1];
    const float* W_Q   = (const float*)d_in[2];
    const float* W_K   = (const float*)d_in[3];
    const float* W_V   = (const float*)d_in[4];
    const float* W_out = (const float*)d_in[5];
    const float* b_out = (const float*)d_in[6];
    float* out = (float*)d_out;

    bf16 *xs, *wqkv, *wos, *qs, *ks, *vs, *cs;
    cudaGetSymbolAddress((void**)&xs, g_xs);
    cudaGetSymbolAddress((void**)&wqkv, g_wqkv);
    cudaGetSymbolAddress((void**)&wos, g_wos);
    cudaGetSymbolAddress((void**)&qs, g_qs);
    cudaGetSymbolAddress((void**)&ks, g_ks);
    cudaGetSymbolAddress((void**)&vs, g_vs);
    cudaGetSymbolAddress((void**)&cs, g_cs);

    cudaFuncSetAttribute(mma_gemm<0>, cudaFuncAttributeMaxDynamicSharedMemorySize, G_SMEM);
    cudaFuncSetAttribute(mma_gemm<1>, cudaFuncAttributeMaxDynamicSharedMemorySize, G_SMEM);
    cudaFuncSetAttribute(attn_mma, cudaFuncAttributeMaxDynamicSharedMemorySize, A_SMEM);

    const int nx4 = MROWS * DMODEL / 4;
    const int nw4 = DMODEL * DMODEL / 4;
    split_kernel<<<(nx4 + 255) / 256, 256>>>(x, xs, nx4);
    dim3 wgrid((nw4 + 255) / 256, 4);
    split_w4<<<wgrid, 256>>>(W_Q, W_K, W_V, W_out, wqkv, wos, nw4);

    dim3 qkvgrid(3 * DMODEL / 256, MROWS / 128);   // (12, 32)
    mma_gemm<0><<<qkvgrid, 256, G_SMEM>>>(xs, wqkv, nullptr, qs, ks, vs, nullptr);

    dim3 agrid(NSEQ / 64, BATCH * NHEAD);          // (32, 32)
    attn_mma<<<agrid, 128, A_SMEM>>>(qs, ks, vs, amask, cs);

    dim3 ogrid(DMODEL / 256, MROWS / 128);         // (4, 32)
    mma_gemm<1><<<ogrid, 256, G_SMEM>>>(cs, wos, out, nullptr, nullptr, nullptr, b_out);
}

// round 9
// speedup vs baseline: 7.4828x; 1.4423x over previous
#include <cuda_runtime.h>
#include <cuda_fp16.h>
#include <cstdint>

// Problem constants
#define BATCH 2
#define NSEQ  2048
#define DMODEL 1024
#define NHEAD 16
#define DK    64
#define MROWS (BATCH * NSEQ)   // 4096

typedef __half fp16;

// ---------------------------------------------------------------------------
// Scratch (allocation-free rule: __device__ globals)
// Activation splits: [rows][2048] = [hi(1024) | lo(1024)] fp16.
// Q/V per-head concat: [rows][2048], head h at h*128: hi dk 0..63, lo 64..127.
// K single fp16: [rows][1024], head h at h*64.
// Weights rounded fp16: wqkv [3072][1024], wos [1024][1024].
// ---------------------------------------------------------------------------
__device__ fp16 g_xs  [MROWS * 2048];
__device__ fp16 g_wqkv[3 * DMODEL * DMODEL];
__device__ fp16 g_wos [DMODEL * DMODEL];
__device__ fp16 g_qs  [MROWS * 2048];
__device__ fp16 g_ks  [MROWS * 1024];
__device__ fp16 g_vs  [MROWS * 2048];
__device__ fp16 g_cs  [MROWS * 2048];

// ---------------------------------------------------------------------------
// PTX helpers (base compute_103 features only)
// ---------------------------------------------------------------------------
__device__ __forceinline__ uint32_t smem_u32(const void* p) {
    uint32_t a;
    asm("{ .reg .u64 t; cvta.to.shared.u64 t, %1; cvt.u32.u64 %0, t; }"
        : "=r"(a) : "l"(p));
    return a;
}
#define CP16(dst, src) \
    asm volatile("cp.async.cg.shared.global [%0], [%1], 16;" \
                 :: "r"(dst), "l"(src))
#define CP_COMMIT() asm volatile("cp.async.commit_group;" ::: "memory")
#define CP_WAIT0()  asm volatile("cp.async.wait_group 0;" ::: "memory")
#define CP_WAIT1()  asm volatile("cp.async.wait_group 1;" ::: "memory")

__device__ __forceinline__ void ldsm4(uint32_t addr, uint32_t& r0, uint32_t& r1,
                                      uint32_t& r2, uint32_t& r3) {
    asm volatile("ldmatrix.sync.aligned.m8n8.x4.shared.b16 {%0,%1,%2,%3}, [%4];"
                 : "=r"(r0), "=r"(r1), "=r"(r2), "=r"(r3) : "r"(addr));
}
__device__ __forceinline__ void ldsm4t(uint32_t addr, uint32_t& r0, uint32_t& r1,
                                       uint32_t& r2, uint32_t& r3) {
    asm volatile("ldmatrix.sync.aligned.m8n8.x4.trans.shared.b16 {%0,%1,%2,%3}, [%4];"
                 : "=r"(r0), "=r"(r1), "=r"(r2), "=r"(r3) : "r"(addr));
}
// D += A*B  (m16n8k16, fp16 in, fp32 accum)
__device__ __forceinline__ void mma16816(float* c, uint32_t a0, uint32_t a1,
                                         uint32_t a2, uint32_t a3,
                                         uint32_t b0, uint32_t b1) {
    asm volatile(
        "mma.sync.aligned.m16n8k16.row.col.f32.f16.f16.f32 "
        "{%0,%1,%2,%3}, {%4,%5,%6,%7}, {%8,%9}, {%0,%1,%2,%3};"
        : "+f"(c[0]), "+f"(c[1]), "+f"(c[2]), "+f"(c[3])
        : "r"(a0), "r"(a1), "r"(a2), "r"(a3), "r"(b0), "r"(b1));
}
__device__ __forceinline__ uint32_t packh(float a, float b) {
    __half2 t = __floats2half2_rn(a, b);
    return *(uint32_t*)&t;
}

// ---------------------------------------------------------------------------
// fp32 [R][1024] -> fp16 split [R][2048] = [hi | lo]
// ---------------------------------------------------------------------------
__device__ __forceinline__ void split_body(const float* __restrict__ in,
                                           fp16* __restrict__ out, int i) {
    float4 v = ((const float4*)in)[i];
    int r = i >> 8;
    int c = (i & 255) * 4;
    fp16 h0 = __float2half_rn(v.x), h1 = __float2half_rn(v.y);
    fp16 h2 = __float2half_rn(v.z), h3 = __float2half_rn(v.w);
    uint32_t* oh = (uint32_t*)(out + (size_t)r * 2048 + c);
    uint32_t* ol = (uint32_t*)(out + (size_t)r * 2048 + 1024 + c);
    oh[0] = packh(__half2float(h0), __half2float(h1));
    oh[1] = packh(__half2float(h2), __half2float(h3));
    ol[0] = packh(v.x - __half2float(h0), v.y - __half2float(h1));
    ol[1] = packh(v.z - __half2float(h2), v.w - __half2float(h3));
}

__global__ __launch_bounds__(256)
void split_kernel(const float* __restrict__ in, fp16* __restrict__ out, int n4) {
    int i = blockIdx.x * blockDim.x + threadIdx.x;
    if (i >= n4) return;
    split_body(in, out, i);
}

// Round the 4 weight matrices to plain fp16 [N][1024] (blockIdx.y selects).
__global__ __launch_bounds__(256)
void round_w4(const float* __restrict__ w0, const float* __restrict__ w1,
              const float* __restrict__ w2, const float* __restrict__ w3,
              fp16* __restrict__ wqkv, fp16* __restrict__ wos, int n4) {
    int i = blockIdx.x * blockDim.x + threadIdx.x;
    if (i >= n4) return;
    int y = blockIdx.y;
    const float* src = (y == 0) ? w0 : (y == 1) ? w1 : (y == 2) ? w2 : w3;
    fp16* dst = (y < 3) ? wqkv + (size_t)y * DMODEL * DMODEL : wos;
    float4 v = ((const float4*)src)[i];
    uint32_t* o = (uint32_t*)(dst + (size_t)i * 4);
    o[0] = packh(v.x, v.y);
    o[1] = packh(v.z, v.w);
}

// ---------------------------------------------------------------------------
// Tensor-core GEMM: C[m][n] = (Ah + Al) . Bh   (fp16 2-term, K' = 2048)
//   chunks c: 0-15 -> Ah (A cols c*64), 16-31 -> Al (A cols 1024+(c-16)*64)
//   B col = (c & 15) * 64 in [N][1024].
// CTA tile 128(M) x 256(N), 256 thr, 8 warps (2x4), warp tile 64x64.
// 3-stage cp.async ring, one __syncthreads per chunk.
// EPI 0: writes q (split), k (rounded), v (split) selected by n.
// EPI 1: fp32 + bias.
// ---------------------------------------------------------------------------
#define G_STRIDE 144                    // bytes per smem row (128B data + pad)
#define G_ASTG   (128 * G_STRIDE)       // 18432
#define G_BSTG   (256 * G_STRIDE)       // 36864
#define G_STAGE  (G_ASTG + G_BSTG)      // 55296
#define G_SMEM   (3 * G_STAGE)          // 165888
#define NCHUNK 32

__device__ __forceinline__ void gemm_prefetch(const fp16* A, const fp16* B,
                                              int m0, int n0, int c,
                                              uint32_t stg, int tid) {
    int ac = (c < 16) ? c * 64 : 1024 + (c - 16) * 64;
    int bc = (c & 15) * 64;
    const uint32_t sa = stg;
    const uint32_t sb = stg + G_ASTG;
#pragma unroll
    for (int it = 0; it < 4; it++) {
        int idx = tid + it * 256;
        int row = idx >> 3, seg = idx & 7;
        CP16(sa + row * G_STRIDE + seg * 16,
             A + (size_t)(m0 + row) * 2048 + ac + seg * 8);
    }
#pragma unroll
    for (int it = 0; it < 8; it++) {
        int idx = tid + it * 256;
        int row = idx >> 3, seg = idx & 7;
        CP16(sb + row * G_STRIDE + seg * 16,
             B + (size_t)(n0 + row) * 1024 + bc + seg * 8);
    }
}

template <int EPI>
__global__ __launch_bounds__(256, 1)
void mma_gemm(const fp16* __restrict__ A, const fp16* __restrict__ B,
              float* __restrict__ Cf,
              fp16* __restrict__ Cq, fp16* __restrict__ Ck, fp16* __restrict__ Cv,
              const float* __restrict__ bias) {
    extern __shared__ char smem[];
    const uint32_t sbase = smem_u32(smem);
    const int tid = threadIdx.x;
    const int w = tid >> 5, L = tid & 31;
    const int g = L >> 2, cq = L & 3;
    const int wm = w >> 2, wn = w & 3;
    const int m0 = blockIdx.y * 128, n0 = blockIdx.x * 256;
    const int quad = L >> 3, l8 = L & 7;

    float acc[4][8][4];
#pragma unroll
    for (int i = 0; i < 4; i++)
#pragma unroll
        for (int j = 0; j < 8; j++)
#pragma unroll
            for (int k = 0; k < 4; k++) acc[i][j][k] = 0.0f;

    gemm_prefetch(A, B, m0, n0, 0, sbase, tid);
    CP_COMMIT();
    gemm_prefetch(A, B, m0, n0, 1, sbase + G_STAGE, tid);
    CP_COMMIT();

    int stage = 0;
    for (int c = 0; c < NCHUNK; c++) {
        if (c == NCHUNK - 1) { CP_WAIT0(); } else { CP_WAIT1(); }
        __syncthreads();
        if (c + 2 < NCHUNK) {
            int s2 = stage + 2; if (s2 >= 3) s2 -= 3;
            gemm_prefetch(A, B, m0, n0, c + 2, sbase + s2 * G_STAGE, tid);
            CP_COMMIT();
        }
        const uint32_t sa = sbase + stage * G_STAGE;
        const uint32_t sb = sa + G_ASTG;

#pragma unroll
        for (int ks = 0; ks < 4; ks++) {
            uint32_t af[4][4];
#pragma unroll
            for (int i = 0; i < 4; i++) {
                int r = wm * 64 + i * 16 + (quad & 1) * 8 + l8;
                int kof = ks * 16 + (quad >> 1) * 8;
                ldsm4(sa + r * G_STRIDE + kof * 2,
                      af[i][0], af[i][1], af[i][2], af[i][3]);
            }
            uint32_t bfr[4][4];
#pragma unroll
            for (int p = 0; p < 4; p++) {
                int nr = wn * 64 + p * 16 + (quad >> 1) * 8 + l8;
                int kof = ks * 16 + (quad & 1) * 8;
                ldsm4(sb + nr * G_STRIDE + kof * 2,
                      bfr[p][0], bfr[p][1], bfr[p][2], bfr[p][3]);
            }
#pragma unroll
            for (int i = 0; i < 4; i++)
#pragma unroll
                for (int p = 0; p < 4; p++) {
                    mma16816(acc[i][2 * p], af[i][0], af[i][1], af[i][2], af[i][3],
                             bfr[p][0], bfr[p][1]);
                    mma16816(acc[i][2 * p + 1], af[i][0], af[i][1], af[i][2], af[i][3],
                             bfr[p][2], bfr[p][3]);
                }
        }
        stage++; if (stage == 3) stage = 0;
    }

    // Epilogue
#pragma unroll
    for (int i = 0; i < 4; i++) {
        int r0 = m0 + wm * 64 + i * 16 + g;
        int r1 = r0 + 8;
#pragma unroll
        for (int j = 0; j < 8; j++) {
            int col = n0 + wn * 64 + j * 8 + 2 * cq;
            float v0 = acc[i][j][0], v1 = acc[i][j][1];
            float v2 = acc[i][j][2], v3 = acc[i][j][3];
            if (EPI == 1) {
                float b0 = bias[col], b1 = bias[col + 1];
                *(float2*)(Cf + (size_t)r0 * 1024 + col) = make_float2(v0 + b0, v1 + b1);
                *(float2*)(Cf + (size_t)r1 * 1024 + col) = make_float2(v2 + b0, v3 + b1);
            } else {
                int mat = col >> 10, cc = col & 1023;
                int head = cc >> 6, dk = cc & 63;
                if (mat == 1) {
                    // K: single rounded fp16 [rows][1024]
                    size_t o0 = (size_t)r0 * 1024 + head * 64 + dk;
                    size_t o1 = (size_t)r1 * 1024 + head * 64 + dk;
                    *(uint32_t*)(Ck + o0) = packh(v0, v1);
                    *(uint32_t*)(Ck + o1) = packh(v2, v3);
                } else {
                    fp16* Cb = (mat == 0) ? Cq : Cv;
                    size_t o0 = (size_t)r0 * 2048 + head * 128 + dk;
                    size_t o1 = (size_t)r1 * 2048 + head * 128 + dk;
                    fp16 h0 = __float2half_rn(v0), h1 = __float2half_rn(v1);
                    fp16 h2 = __float2half_rn(v2), h3 = __float2half_rn(v3);
                    *(uint32_t*)(Cb + o0) = packh(__half2float(h0), __half2float(h1));
                    *(uint32_t*)(Cb + o0 + 64) = packh(v0 - __half2float(h0),
                                                       v1 - __half2float(h1));
                    *(uint32_t*)(Cb + o1) = packh(__half2float(h2), __half2float(h3));
                    *(uint32_t*)(Cb + o1 + 64) = packh(v2 - __half2float(h2),
                                                       v3 - __half2float(h3));
                }
            }
        }
    }
}

// ---------------------------------------------------------------------------
// Tensor-core flash attention, fp16 2-term.
// Grid (32 qblocks, 32 bh). CTA = 128 thr = 4 warps; warp owns 16 query rows.
// QK^T: 8 k-steps ((qh+ql) x Kh, K fragments reused). PV: Ph x (Vh + Vl).
// Output: ctx hi/lo fp16 into CS row-concat layout [ch(1024) | cl(1024)].
// ---------------------------------------------------------------------------
#define K_STRIDE 144                  // 64 fp16 per key row + pad
#define V_STRIDE 272                  // 128 fp16 (vh|vl) per key row + pad
#define K_TILE   (64 * K_STRIDE)      // 9216
#define V_TILE   (64 * V_STRIDE)      // 17408
#define A_STAGE  (K_TILE + V_TILE)    // 26624
#define A_PAD_OFF (2 * A_STAGE)       // 53248
#define A_SMEM   (A_PAD_OFF + 512)    // 53760

__device__ __forceinline__ void attn_prefetch(const fp16* KS, const fp16* VS,
                                              const int* amask, char* smem,
                                              uint32_t sbase, int b, int h,
                                              int kt, int st, int tid) {
    const uint32_t kb = sbase + st * A_STAGE;
    const uint32_t vb = kb + K_TILE;
    const fp16* ksrc = KS + ((size_t)(b * NSEQ + kt)) * 1024 + h * 64;
    const fp16* vsrc = VS + ((size_t)(b * NSEQ + kt)) * 2048 + h * 128;
#pragma unroll
    for (int it = 0; it < 4; it++) {
        int idx = tid + it * 128;
        int row = idx >> 3, seg = idx & 7;
        CP16(kb + row * K_STRIDE + seg * 16, ksrc + (size_t)row * 1024 + seg * 8);
    }
#pragma unroll
    for (int it = 0; it < 8; it++) {
        int idx = tid + it * 128;
        int row = idx >> 4, seg = idx & 15;
        CP16(vb + row * V_STRIDE + seg * 16, vsrc + (size_t)row * 2048 + seg * 8);
    }
    if (tid < 64) {
        float pv = amask[b * NSEQ + kt + tid] ? 0.0f : -1e30f;
        *(float*)(smem + A_PAD_OFF + st * 256 + tid * 4) = pv;
    }
}

__global__ __launch_bounds__(128, 4)
void attn_mma(const fp16* __restrict__ QS, const fp16* __restrict__ KS,
              const fp16* __restrict__ VS, const int* __restrict__ amask,
              fp16* __restrict__ CS) {
    extern __shared__ char smem[];
    const uint32_t sbase = smem_u32(smem);
    const int tid = threadIdx.x;
    const int w = tid >> 5, L = tid & 31;
    const int g = L >> 2, cq = L & 3;
    const int quad = L >> 3, l8 = L & 7;
    const int qb = 31 - blockIdx.x;          // big blocks first
    const int m0 = qb * 64;
    const int bh = blockIdx.y;
    const int b = bh >> 4, h = bh & 15;
    const int rowA = m0 + w * 16 + g;
    const int rowB = rowA + 8;

    // Q fragments: qa[0..3] = qh k-steps, qa[4..7] = ql k-steps
    uint32_t qa[8][4];
    {
        const fp16* qA = QS + (size_t)(b * NSEQ + rowA) * 2048 + h * 128;
        const fp16* qB = QS + (size_t)(b * NSEQ + rowB) * 2048 + h * 128;
#pragma unroll
        for (int s = 0; s < 8; s++) {
            qa[s][0] = *(const uint32_t*)(qA + s * 16 + 2 * cq);
            qa[s][1] = *(const uint32_t*)(qB + s * 16 + 2 * cq);
            qa[s][2] = *(const uint32_t*)(qA + s * 16 + 2 * cq + 8);
            qa[s][3] = *(const uint32_t*)(qB + s * 16 + 2 * cq + 8);
        }
    }

    float co[8][4];
#pragma unroll
    for (int d = 0; d < 8; d++)
#pragma unroll
        for (int k = 0; k < 4; k++) co[d][k] = 0.0f;
    float mx0 = -1e30f, mx1 = -1e30f;
    float l0 = 0.0f, l1 = 0.0f;

    const int nt = qb + 1;
    attn_prefetch(KS, VS, amask, smem, sbase, b, h, 0, 0, tid);
    CP_COMMIT();

    for (int t = 0; t < nt; t++) {
        const int kt = t * 64;
        const int st = t & 1;
        CP_WAIT0();
        __syncthreads();
        if (t + 1 < nt) {
            attn_prefetch(KS, VS, amask, smem, sbase, b, h, (t + 1) * 64,
                          (t + 1) & 1, tid);
            CP_COMMIT();
        }

        const uint32_t kb = sbase + st * A_STAGE;
        const uint32_t vb = kb + K_TILE;
        const float* padf = (const float*)(smem + A_PAD_OFF + st * 256);

        // ---- scores: (qh + ql) x Kh, K fragments loaded once ----
        float sc[8][4];
#pragma unroll
        for (int f = 0; f < 8; f++)
#pragma unroll
            for (int k = 0; k < 4; k++) sc[f][k] = 0.0f;

#pragma unroll
        for (int ks = 0; ks < 4; ks++) {
            const int kof = ks * 16 + (quad & 1) * 8;
#pragma unroll
            for (int p = 0; p < 4; p++) {
                uint32_t b0, b1, b2, b3;
                int krow = p * 16 + (quad >> 1) * 8 + l8;
                ldsm4(kb + krow * K_STRIDE + kof * 2, b0, b1, b2, b3);
                mma16816(sc[2 * p], qa[ks][0], qa[ks][1], qa[ks][2], qa[ks][3], b0, b1);
                mma16816(sc[2 * p + 1], qa[ks][0], qa[ks][1], qa[ks][2], qa[ks][3], b2, b3);
                mma16816(sc[2 * p], qa[ks + 4][0], qa[ks + 4][1], qa[ks + 4][2],
                         qa[ks + 4][3], b0, b1);
                mma16816(sc[2 * p + 1], qa[ks + 4][0], qa[ks + 4][1], qa[ks + 4][2],
                         qa[ks + 4][3], b2, b3);
            }
        }

        // ---- mask + scale + row max ----
        const bool diag = (kt == m0);
        float mn0 = mx0, mn1 = mx1;
#pragma unroll
        for (int f = 0; f < 8; f++) {
            float2 pd = *(const float2*)(padf + f * 8 + 2 * cq);
            int k0 = kt + f * 8 + 2 * cq;
            float s0 = sc[f][0] * 0.125f + pd.x;
            float s1 = sc[f][1] * 0.125f + pd.y;
            float s2 = sc[f][2] * 0.125f + pd.x;
            float s3 = sc[f][3] * 0.125f + pd.y;
            if (diag) {
                if (k0 > rowA) s0 = -1e30f;
                if (k0 + 1 > rowA) s1 = -1e30f;
                if (k0 > rowB) s2 = -1e30f;
                if (k0 + 1 > rowB) s3 = -1e30f;
            }
            sc[f][0] = s0; sc[f][1] = s1; sc[f][2] = s2; sc[f][3] = s3;
            mn0 = fmaxf(mn0, fmaxf(s0, s1));
            mn1 = fmaxf(mn1, fmaxf(s2, s3));
        }
        mn0 = fmaxf(mn0, __shfl_xor_sync(0xffffffffu, mn0, 1));
        mn0 = fmaxf(mn0, __shfl_xor_sync(0xffffffffu, mn0, 2));
        mn1 = fmaxf(mn1, __shfl_xor_sync(0xffffffffu, mn1, 1));
        mn1 = fmaxf(mn1, __shfl_xor_sync(0xffffffffu, mn1, 2));

        const float corr0 = __expf(mx0 - mn0);
        const float corr1 = __expf(mx1 - mn1);
        mx0 = mn0; mx1 = mn1;
        l0 *= corr0; l1 *= corr1;
#pragma unroll
        for (int d = 0; d < 8; d++) {
            co[d][0] *= corr0; co[d][1] *= corr0;
            co[d][2] *= corr1; co[d][3] *= corr1;
        }

        // ---- exp + P fragments (fp16 rounded, no split) ----
        uint32_t phA[8], phB[8];
#pragma unroll
        for (int f = 0; f < 8; f++) {
            float p0 = __expf(sc[f][0] - mn0), p1 = __expf(sc[f][1] - mn0);
            float p2 = __expf(sc[f][2] - mn1), p3 = __expf(sc[f][3] - mn1);
            l0 += p0 + p1; l1 += p2 + p3;
            phA[f] = packh(p0, p1);
            phB[f] = packh(p2, p3);
        }

        // ---- O += Ph @ (Vh + Vl) ----
#pragma unroll
        for (int kk = 0; kk < 4; kk++) {
            uint32_t a0 = phA[2 * kk], a1 = phB[2 * kk];
            uint32_t a2 = phA[2 * kk + 1], a3 = phB[2 * kk + 1];
#pragma unroll
            for (int dp = 0; dp < 4; dp++) {
                int key = kk * 16 + (quad & 1) * 8 + l8;
                int dkc = (2 * dp + (quad >> 1)) * 8;
                uint32_t vh0, vh1, vh2, vh3, vl0, vl1, vl2, vl3;
                ldsm4t(vb + key * V_STRIDE + dkc * 2, vh0, vh1, vh2, vh3);
                ldsm4t(vb + key * V_STRIDE + 128 + dkc * 2, vl0, vl1, vl2, vl3);
                mma16816(co[2 * dp],     a0, a1, a2, a3, vh0, vh1);
                mma16816(co[2 * dp + 1], a0, a1, a2, a3, vh2, vh3);
                mma16816(co[2 * dp],     a0, a1, a2, a3, vl0, vl1);
                mma16816(co[2 * dp + 1], a0, a1, a2, a3, vl2, vl3);
            }
        }
    }

    // ---- finalize ----
    l0 += __shfl_xor_sync(0xffffffffu, l0, 1);
    l0 += __shfl_xor_sync(0xffffffffu, l0, 2);
    l1 += __shfl_xor_sync(0xffffffffu, l1, 1);
    l1 += __shfl_xor_sync(0xffffffffu, l1, 2);
    const float inv0 = 1.0f / l0, inv1 = 1.0f / l1;

#pragma unroll
    for (int d = 0; d < 8; d++) {
        int dk = d * 8 + 2 * cq;
        size_t bA = (size_t)(b * NSEQ + rowA) * 2048 + h * 64 + dk;
        size_t bB = (size_t)(b * NSEQ + rowB) * 2048 + h * 64 + dk;
        float v0 = co[d][0] * inv0, v1 = co[d][1] * inv0;
        float v2 = co[d][2] * inv1, v3 = co[d][3] * inv1;
        fp16 h0 = __float2half_rn(v0), h1 = __float2half_rn(v1);
        fp16 h2 = __float2half_rn(v2), h3 = __float2half_rn(v3);
        *(uint32_t*)(CS + bA) = packh(__half2float(h0), __half2float(h1));
        *(uint32_t*)(CS + bA + 1024) = packh(v0 - __half2float(h0),
                                             v1 - __half2float(h1));
        *(uint32_t*)(CS + bB) = packh(__half2float(h2), __half2float(h3));
        *(uint32_t*)(CS + bB + 1024) = packh(v2 - __half2float(h2),
                                             v3 - __half2float(h3));
    }
}

// ---------------------------------------------------------------------------
// Launch
// ---------------------------------------------------------------------------
extern "C" void kernel_launch(void* const* d_in, const int* in_sizes, int n_in,
                              void* d_out, int out_size) {
    const float* x     = (const float*)d_in[0];
    const int*   amask = (const int*)d_in[1];
    const float* W_Q   = (const float*)d_in[2];
    const float* W_K   = (const float*)d_in[3];
    const float* W_V   = (const float*)d_in[4];
    const float* W_out = (const float*)d_in[5];
    const float* b_out = (const float*)d_in[6];
    float* out = (float*)d_out;

    fp16 *xs, *wqkv, *wos, *qs, *ks, *vs, *cs;
    cudaGetSymbolAddress((void**)&xs, g_xs);
    cudaGetSymbolAddress((void**)&wqkv, g_wqkv);
    cudaGetSymbolAddress((void**)&wos, g_wos);
    cudaGetSymbolAddress((void**)&qs, g_qs);
    cudaGetSymbolAddress((void**)&ks, g_ks);
    cudaGetSymbolAddress((void**)&vs, g_vs);
    cudaGetSymbolAddress((void**)&cs, g_cs);

    cudaFuncSetAttribute(mma_gemm<0>, cudaFuncAttributeMaxDynamicSharedMemorySize, G_SMEM);
    cudaFuncSetAttribute(mma_gemm<1>, cudaFuncAttributeMaxDynamicSharedMemorySize, G_SMEM);
    cudaFuncSetAttribute(attn_mma, cudaFuncAttributeMaxDynamicSharedMemorySize, A_SMEM);

    const int nx4 = MROWS * DMODEL / 4;
    const int nw4 = DMODEL * DMODEL / 4;
    split_kernel<<<(nx4 + 255) / 256, 256>>>(x, xs, nx4);
    dim3 wgrid((nw4 + 255) / 256, 4);
    round_w4<<<wgrid, 256>>>(W_Q, W_K, W_V, W_out, wqkv, wos, nw4);

    dim3 qkvgrid(3 * DMODEL / 256, MROWS / 128);   // (12, 32)
    mma_gemm<0><<<qkvgrid, 256, G_SMEM>>>(xs, wqkv, nullptr, qs, ks, vs, nullptr);

    dim3 agrid(NSEQ / 64, BATCH * NHEAD);          // (32, 32)
    attn_mma<<<agrid, 128, A_SMEM>>>(qs, ks, vs, amask, cs);

    dim3 ogrid(DMODEL / 256, MROWS / 128);         // (4, 32)
    mma_gemm<1><<<ogrid, 256, G_SMEM>>>(cs, wos, out, nullptr, nullptr, nullptr, b_out);
}